// round 1
// baseline (speedup 1.0000x reference)
#include <cuda_runtime.h>
#include <math_constants.h>

#define BB 16
#define SS 4096
#define HH 1024

// Scratch (allocation-free rule: __device__ globals)
__device__ float g_v[BB * HH];   // v[b,h] = sum_g hidden[b,g] * W[g,h]
__device__ float g_c[BB];        // c[b]   = hidden[b] . bias
__device__ float g_e[BB * SS];   // attn energies before softmax

// ---------------------------------------------------------------------------
// Kernel 1: v = hidden @ W  (16x1024 @ 1024x1024 read as W[g,h]), plus c[b].
// grid: (BB, HH/256), block: 256.  Thread t computes v[b, hc*256 + t]:
// inner loop over g reads W[g, h] -> consecutive h across lanes = coalesced.
// ---------------------------------------------------------------------------
__global__ void proj_kernel(const float* __restrict__ hidden,
                            const float* __restrict__ W,
                            const float* __restrict__ bias) {
    __shared__ float sh[HH];
    __shared__ float red[256];
    const int b  = blockIdx.x;
    const int hc = blockIdx.y;

    for (int i = threadIdx.x; i < HH; i += blockDim.x)
        sh[i] = hidden[b * HH + i];
    __syncthreads();

    const int h = hc * 256 + threadIdx.x;
    // 4 accumulators to break the serial FFMA dependency chain
    float a0 = 0.f, a1 = 0.f, a2 = 0.f, a3 = 0.f;
    #pragma unroll 4
    for (int g = 0; g < HH; g += 4) {
        a0 += sh[g + 0] * W[(g + 0) * HH + h];
        a1 += sh[g + 1] * W[(g + 1) * HH + h];
        a2 += sh[g + 2] * W[(g + 2) * HH + h];
        a3 += sh[g + 3] * W[(g + 3) * HH + h];
    }
    g_v[b * HH + h] = (a0 + a1) + (a2 + a3);

    if (hc == 0) {
        float p = 0.f;
        for (int i = threadIdx.x; i < HH; i += 256)
            p += sh[i] * bias[i];
        red[threadIdx.x] = p;
        __syncthreads();
        for (int s = 128; s > 0; s >>= 1) {
            if (threadIdx.x < s) red[threadIdx.x] += red[threadIdx.x + s];
            __syncthreads();
        }
        if (threadIdx.x == 0) g_c[b] = red[0];
    }
}

// ---------------------------------------------------------------------------
// Kernel 2 (dominant, HBM-bound): e[b,s] = enc[b,s,:] . v[b,:] + c[b]
// grid: (SS/8, BB), block: 256 (8 warps, one warp per s-row).
// float4 loads: each warp iteration reads 512B contiguous of enc.
// ---------------------------------------------------------------------------
__global__ void energy_kernel(const float* __restrict__ enc) {
    __shared__ float sv[HH];
    const int b = blockIdx.y;
    for (int i = threadIdx.x; i < HH; i += blockDim.x)
        sv[i] = g_v[b * HH + i];
    __syncthreads();

    const int warp = threadIdx.x >> 5;
    const int lane = threadIdx.x & 31;
    const int s = blockIdx.x * 8 + warp;

    const float4* __restrict__ row =
        reinterpret_cast<const float4*>(enc + ((size_t)b * SS + s) * HH);
    const float4* vv = reinterpret_cast<const float4*>(sv);

    float acc = 0.f;
    #pragma unroll
    for (int i = 0; i < 8; i++) {
        const float4 e4 = row[lane + i * 32];
        const float4 v4 = vv[lane + i * 32];
        acc += e4.x * v4.x + e4.y * v4.y + e4.z * v4.z + e4.w * v4.w;
    }
    #pragma unroll
    for (int off = 16; off > 0; off >>= 1)
        acc += __shfl_xor_sync(0xffffffffu, acc, off);
    if (lane == 0)
        g_e[b * SS + s] = acc + g_c[b];
}

// ---------------------------------------------------------------------------
// Kernel 3: softmax over S per batch. grid: BB, block: 512 (8 values/thread).
// ---------------------------------------------------------------------------
__global__ void softmax_kernel(float* __restrict__ out) {
    __shared__ float red[512];
    const int b = blockIdx.x;
    const int t = threadIdx.x;
    const int base = b * SS;

    float vals[8];
    float m = -CUDART_INF_F;
    #pragma unroll
    for (int i = 0; i < 8; i++) {
        vals[i] = g_e[base + t + i * 512];
        m = fmaxf(m, vals[i]);
    }
    red[t] = m;
    __syncthreads();
    for (int s = 256; s > 0; s >>= 1) {
        if (t < s) red[t] = fmaxf(red[t], red[t + s]);
        __syncthreads();
    }
    m = red[0];
    __syncthreads();

    float sum = 0.f;
    #pragma unroll
    for (int i = 0; i < 8; i++) {
        vals[i] = expf(vals[i] - m);
        sum += vals[i];
    }
    red[t] = sum;
    __syncthreads();
    for (int s = 256; s > 0; s >>= 1) {
        if (t < s) red[t] += red[t + s];
        __syncthreads();
    }
    const float inv = 1.f / red[0];
    #pragma unroll
    for (int i = 0; i < 8; i++)
        out[base + t + i * 512] = vals[i] * inv;
}

// ---------------------------------------------------------------------------
// Inputs (setup_inputs order): hidden[B,H] f32, encoder_outputs[B,S,H] f32,
// W[H,H] f32, b[H] f32.  Output: [B,1,S] f32.
// ---------------------------------------------------------------------------
extern "C" void kernel_launch(void* const* d_in, const int* in_sizes, int n_in,
                              void* d_out, int out_size) {
    const float* hidden = (const float*)d_in[0];
    const float* enc    = (const float*)d_in[1];
    const float* W      = (const float*)d_in[2];
    const float* bias   = (const float*)d_in[3];
    float* out = (float*)d_out;

    proj_kernel<<<dim3(BB, HH / 256), 256>>>(hidden, W, bias);
    energy_kernel<<<dim3(SS / 8, BB), 256>>>(enc);
    softmax_kernel<<<BB, 512>>>(out);
}

// round 2
// speedup vs baseline: 3.1004x; 3.1004x over previous
#include <cuda_runtime.h>
#include <math_constants.h>

#define BB 16
#define SS 4096
#define HH 1024
#define GSPLIT 32           // g-chunks of 32
#define GCHUNK (HH / GSPLIT)

// Scratch (allocation-free rule: __device__ globals)
__device__ float g_vp[GSPLIT][BB * HH]; // partial v per g-chunk
__device__ float g_v[BB * HH];          // v[b,h] = sum_g hidden[b,g] * W[g,h]
__device__ float g_e[BB * SS];          // attn energies before softmax

// ---------------------------------------------------------------------------
// Kernel 1: split-K projection partials.
// grid: (HH/128, GSPLIT), block: 128. Thread owns one h column, accumulates
// all 16 batches over a 32-row g-chunk of W. Every W element is loaded once
// and reused 16x; all 32 g-loads per thread are independent (full MLP).
// ---------------------------------------------------------------------------
__global__ void proj_partial(const float* __restrict__ hidden,
                             const float* __restrict__ W) {
    __shared__ float sh[GCHUNK * BB];   // sh[g*BB + b] = hidden[b, g0+g]
    const int hc = blockIdx.x;
    const int gc = blockIdx.y;
    const int g0 = gc * GCHUNK;
    const int h  = hc * 128 + threadIdx.x;

    for (int i = threadIdx.x; i < GCHUNK * BB; i += 128) {
        const int g = i / BB, b = i % BB;
        sh[i] = hidden[b * HH + g0 + g];
    }
    __syncthreads();

    float acc[BB];
    #pragma unroll
    for (int b = 0; b < BB; b++) acc[b] = 0.f;

    #pragma unroll
    for (int g = 0; g < GCHUNK; g++) {
        const float w = W[(size_t)(g0 + g) * HH + h];   // coalesced
        #pragma unroll
        for (int b = 0; b < BB; b++)
            acc[b] += sh[g * BB + b] * w;               // smem broadcast
    }

    #pragma unroll
    for (int b = 0; b < BB; b++)
        g_vp[gc][b * HH + h] = acc[b];
}

// ---------------------------------------------------------------------------
// Kernel 2: deterministic reduction of the 32 partials. grid: 128, block: 128.
// 32 independent strided loads per thread -> latency fully overlapped.
// ---------------------------------------------------------------------------
__global__ void proj_reduce() {
    const int idx = blockIdx.x * 128 + threadIdx.x;     // 0 .. 16383
    float v = 0.f;
    #pragma unroll
    for (int gc = 0; gc < GSPLIT; gc++)
        v += g_vp[gc][idx];
    g_v[idx] = v;
}

// ---------------------------------------------------------------------------
// Kernel 3 (dominant, HBM-bound): e[b,s] = enc[b,s,:] . v[b,:]
// (bias term is constant over s -> cancels in softmax, so it is dropped)
// grid: (SS/8, BB), block: 256 (one warp per s-row), float4 loads.
// ---------------------------------------------------------------------------
__global__ void energy_kernel(const float* __restrict__ enc) {
    __shared__ float sv[HH];
    const int b = blockIdx.y;
    for (int i = threadIdx.x; i < HH; i += blockDim.x)
        sv[i] = g_v[b * HH + i];
    __syncthreads();

    const int warp = threadIdx.x >> 5;
    const int lane = threadIdx.x & 31;
    const int s = blockIdx.x * 8 + warp;

    const float4* __restrict__ row =
        reinterpret_cast<const float4*>(enc + ((size_t)b * SS + s) * HH);
    const float4* vv = reinterpret_cast<const float4*>(sv);

    float acc = 0.f;
    #pragma unroll
    for (int i = 0; i < 8; i++) {
        const float4 e4 = __ldcs(&row[lane + i * 32]);  // streaming: don't pollute L2
        const float4 v4 = vv[lane + i * 32];
        acc += e4.x * v4.x + e4.y * v4.y + e4.z * v4.z + e4.w * v4.w;
    }
    #pragma unroll
    for (int off = 16; off > 0; off >>= 1)
        acc += __shfl_xor_sync(0xffffffffu, acc, off);
    if (lane == 0)
        g_e[b * SS + s] = acc;
}

// ---------------------------------------------------------------------------
// Kernel 4: softmax over S per batch. grid: BB, block: 512 (8 values/thread).
// ---------------------------------------------------------------------------
__global__ void softmax_kernel(float* __restrict__ out) {
    __shared__ float red[512];
    const int b = blockIdx.x;
    const int t = threadIdx.x;
    const int base = b * SS;

    float vals[8];
    float m = -CUDART_INF_F;
    #pragma unroll
    for (int i = 0; i < 8; i++) {
        vals[i] = g_e[base + t + i * 512];
        m = fmaxf(m, vals[i]);
    }
    red[t] = m;
    __syncthreads();
    for (int s = 256; s > 0; s >>= 1) {
        if (t < s) red[t] = fmaxf(red[t], red[t + s]);
        __syncthreads();
    }
    m = red[0];
    __syncthreads();

    float sum = 0.f;
    #pragma unroll
    for (int i = 0; i < 8; i++) {
        vals[i] = expf(vals[i] - m);
        sum += vals[i];
    }
    red[t] = sum;
    __syncthreads();
    for (int s = 256; s > 0; s >>= 1) {
        if (t < s) red[t] += red[t + s];
        __syncthreads();
    }
    const float inv = 1.f / red[0];
    #pragma unroll
    for (int i = 0; i < 8; i++)
        out[base + t + i * 512] = vals[i] * inv;
}

// ---------------------------------------------------------------------------
// Inputs (setup_inputs order): hidden[B,H] f32, encoder_outputs[B,S,H] f32,
// W[H,H] f32, b[H] f32.  Output: [B,1,S] f32.
// ---------------------------------------------------------------------------
extern "C" void kernel_launch(void* const* d_in, const int* in_sizes, int n_in,
                              void* d_out, int out_size) {
    const float* hidden = (const float*)d_in[0];
    const float* enc    = (const float*)d_in[1];
    const float* W      = (const float*)d_in[2];
    // d_in[3] = bias: unused (constant offset cancels in softmax)
    float* out = (float*)d_out;

    proj_partial<<<dim3(HH / 128, GSPLIT), 128>>>(hidden, W);
    proj_reduce<<<128, 128>>>();
    energy_kernel<<<dim3(SS / 8, BB), 256>>>(enc);
    softmax_kernel<<<BB, 512>>>(out);
}

// round 6
// speedup vs baseline: 3.1043x; 1.0012x over previous
#include <cuda_runtime.h>
#include <math_constants.h>

#define BB 16
#define SS 4096
#define HH 1024
#define GSPLIT 64           // g-chunks of 16
#define GCHUNK (HH / GSPLIT)

// Scratch (allocation-free rule: __device__ globals)
__device__ float g_vp[GSPLIT][BB * HH]; // partial v per g-chunk
__device__ float g_v[BB * HH];          // v[b,h] = sum_g hidden[b,g] * W[g,h]
__device__ float g_e[BB * SS];          // attn energies before softmax

// ---------------------------------------------------------------------------
// Kernel 1: split-K projection partials.
// grid: (HH/256, GSPLIT) = (4,64) = 256 blocks, block: 256 (8 warps).
// Thread owns one h column, accumulates all 16 batches over a 16-row g-chunk
// of W. W is read exactly once; all 16 g-loads per thread are independent.
// ---------------------------------------------------------------------------
__global__ void proj_partial(const float* __restrict__ hidden,
                             const float* __restrict__ W) {
    __shared__ float sh[GCHUNK * BB];   // sh[g*BB + b] = hidden[b, g0+g]
    const int hc = blockIdx.x;
    const int gc = blockIdx.y;
    const int g0 = gc * GCHUNK;
    const int h  = hc * 256 + threadIdx.x;

    if (threadIdx.x < GCHUNK * BB) {
        const int g = threadIdx.x / BB, b = threadIdx.x % BB;
        sh[threadIdx.x] = hidden[b * HH + g0 + g];
    }
    __syncthreads();

    float acc[BB];
    #pragma unroll
    for (int b = 0; b < BB; b++) acc[b] = 0.f;

    #pragma unroll
    for (int g = 0; g < GCHUNK; g++) {
        const float w = W[(size_t)(g0 + g) * HH + h];   // coalesced, read once
        #pragma unroll
        for (int b = 0; b < BB; b++)
            acc[b] += sh[g * BB + b] * w;               // smem broadcast
    }

    #pragma unroll
    for (int b = 0; b < BB; b++)
        g_vp[gc][b * HH + h] = acc[b];
}

// ---------------------------------------------------------------------------
// Kernel 2: deterministic reduction of the 64 partials. grid: 128, block: 128.
// 64 independent strided loads per thread -> latency fully overlapped.
// Streaming loads: g_vp is dead after this, keep it out of L2.
// ---------------------------------------------------------------------------
__global__ void proj_reduce() {
    const int idx = blockIdx.x * 128 + threadIdx.x;     // 0 .. 16383
    float v = 0.f;
    #pragma unroll
    for (int gc = 0; gc < GSPLIT; gc++)
        v += __ldcs(&g_vp[gc][idx]);
    g_v[idx] = v;
}

// ---------------------------------------------------------------------------
// Kernel 3 (dominant, HBM-bound): e[b,s] = enc[b,s,:] . v[b,:]
// (bias term is constant over s -> cancels in softmax, so it is dropped)
// grid: (SS/8, BB), block: 256 (one warp per s-row), float4 streaming loads.
// ---------------------------------------------------------------------------
__global__ void energy_kernel(const float* __restrict__ enc) {
    __shared__ float sv[HH];
    const int b = blockIdx.y;
    for (int i = threadIdx.x; i < HH; i += blockDim.x)
        sv[i] = g_v[b * HH + i];
    __syncthreads();

    const int warp = threadIdx.x >> 5;
    const int lane = threadIdx.x & 31;
    const int s = blockIdx.x * 8 + warp;

    const float4* __restrict__ row =
        reinterpret_cast<const float4*>(enc + ((size_t)b * SS + s) * HH);
    const float4* vv = reinterpret_cast<const float4*>(sv);

    float acc = 0.f;
    #pragma unroll
    for (int i = 0; i < 8; i++) {
        const float4 e4 = __ldcs(&row[lane + i * 32]);  // streaming: don't pollute L2
        const float4 v4 = vv[lane + i * 32];
        acc += e4.x * v4.x + e4.y * v4.y + e4.z * v4.z + e4.w * v4.w;
    }
    #pragma unroll
    for (int off = 16; off > 0; off >>= 1)
        acc += __shfl_xor_sync(0xffffffffu, acc, off);
    if (lane == 0)
        g_e[b * SS + s] = acc;
}

// ---------------------------------------------------------------------------
// Kernel 4: softmax over S per batch. grid: BB, block: 1024 (float4/thread).
// Warp-shuffle reductions + one 32-entry smem stage; __expf (MUFU.EX2).
// ---------------------------------------------------------------------------
__global__ void softmax_kernel(float* __restrict__ out) {
    __shared__ float red[32];
    const int b    = blockIdx.x;
    const int t    = threadIdx.x;
    const int warp = t >> 5;
    const int lane = t & 31;

    const float4* ein  = reinterpret_cast<const float4*>(g_e + b * SS);
    float4*       oout = reinterpret_cast<float4*>(out + b * SS);

    float4 v = ein[t];

    // ---- max reduction ----
    float m = fmaxf(fmaxf(v.x, v.y), fmaxf(v.z, v.w));
    #pragma unroll
    for (int off = 16; off > 0; off >>= 1)
        m = fmaxf(m, __shfl_xor_sync(0xffffffffu, m, off));
    if (lane == 0) red[warp] = m;
    __syncthreads();
    if (warp == 0) {
        float r = red[lane];
        #pragma unroll
        for (int off = 16; off > 0; off >>= 1)
            r = fmaxf(r, __shfl_xor_sync(0xffffffffu, r, off));
        if (lane == 0) red[0] = r;
    }
    __syncthreads();
    m = red[0];
    __syncthreads();

    // ---- exp + sum reduction ----
    v.x = __expf(v.x - m); v.y = __expf(v.y - m);
    v.z = __expf(v.z - m); v.w = __expf(v.w - m);
    float s = (v.x + v.y) + (v.z + v.w);
    #pragma unroll
    for (int off = 16; off > 0; off >>= 1)
        s += __shfl_xor_sync(0xffffffffu, s, off);
    if (lane == 0) red[warp] = s;
    __syncthreads();
    if (warp == 0) {
        float r = red[lane];
        #pragma unroll
        for (int off = 16; off > 0; off >>= 1)
            r += __shfl_xor_sync(0xffffffffu, r, off);
        if (lane == 0) red[0] = r;
    }
    __syncthreads();
    const float inv = 1.f / red[0];

    v.x *= inv; v.y *= inv; v.z *= inv; v.w *= inv;
    oout[t] = v;
}

// ---------------------------------------------------------------------------
// Inputs (setup_inputs order): hidden[B,H] f32, encoder_outputs[B,S,H] f32,
// W[H,H] f32, b[H] f32.  Output: [B,1,S] f32.
// ---------------------------------------------------------------------------
extern "C" void kernel_launch(void* const* d_in, const int* in_sizes, int n_in,
                              void* d_out, int out_size) {
    const float* hidden = (const float*)d_in[0];
    const float* enc    = (const float*)d_in[1];
    const float* W      = (const float*)d_in[2];
    // d_in[3] = bias: unused (constant offset cancels in softmax)
    float* out = (float*)d_out;

    proj_partial<<<dim3(HH / 256, GSPLIT), 256>>>(hidden, W);
    proj_reduce<<<128, 128>>>();
    energy_kernel<<<dim3(SS / 8, BB), 256>>>(enc);
    softmax_kernel<<<BB, 1024>>>(out);
}